// round 15
// baseline (speedup 1.0000x reference)
#include <cuda_runtime.h>
#include <cuda_fp16.h>
#include <cuda_bf16.h>

#define NN 4
#define NQ 256
#define NV 512
#define NE 256

// Scratch (allocation-free requirement)
__device__ float g_expl[NN * NQ * NV];       // exp(logit/t)  (2 MB)
__device__ float g_denp[NN * NQ * 16];       // per-32v denominator partials
__device__ float g_pvp[4][NN * NQ * NE];     // split-4 partials of exp@memory (4 MB)
__device__ float g_heads[NN * NQ * NE];      // normalized, leaky heads (1 MB)
__device__ float g_rdp[4][NN * NQ * NE];     // split-4 partials of heads@Wr^T (4 MB)

// ---------------------------------------------------------------------------
// helpers
// ---------------------------------------------------------------------------
__device__ __forceinline__ uint4 pack8(const float4 a, const float4 b) {
    __half2 h0 = __floats2half2_rn(a.x, a.y);
    __half2 h1 = __floats2half2_rn(a.z, a.w);
    __half2 h2 = __floats2half2_rn(b.x, b.y);
    __half2 h3 = __floats2half2_rn(b.z, b.w);
    uint4 r;
    r.x = *reinterpret_cast<unsigned*>(&h0);
    r.y = *reinterpret_cast<unsigned*>(&h1);
    r.z = *reinterpret_cast<unsigned*>(&h2);
    r.w = *reinterpret_cast<unsigned*>(&h3);
    return r;
}

__device__ __forceinline__ __half2 u2h(unsigned u) {
    return *reinterpret_cast<__half2*>(&u);
}

__device__ __forceinline__ __half2 wtanh(unsigned cv, unsigned qv, unsigned wv) {
    __half2 s = __hadd2(u2h(qv), u2h(cv));
    unsigned su = *reinterpret_cast<unsigned*>(&s);
    unsigned tu;
    asm("tanh.approx.f16x2 %0, %1;" : "=r"(tu) : "r"(su));
    return __hmul2(u2h(tu), u2h(wv));
}

// ---------------------------------------------------------------------------
// K1: e[n,q,v] = exp( (sum_e w*tanh(q+c) + b) / t ), plus per-32v denom
// partials. TWO q-rows per warp: two independent dependency chains per
// iteration sharing one c-tile load (ILP fix; ct tile unchanged at 17 KB).
// Block = 16 q-rows x 32 v.
// ---------------------------------------------------------------------------
__global__ void __launch_bounds__(256) k_logits(
    const float* __restrict__ q, const float* __restrict__ c,
    const float* __restrict__ wl, const float* __restrict__ bl_p,
    const float* __restrict__ temp_p)
{
    __shared__ uint4 ct[32][33];    // 16.9 KB, [e-octet][v]
    __shared__ uint4 qs[16][32];    // 8 KB
    __shared__ uint4 ws[32];        // 512 B

    const int n = blockIdx.z;
    const int vb = blockIdx.y;              // 0..15, 32 v each
    const int qbase = blockIdx.x * 16;
    const int tid = threadIdx.x;
    const int w = tid >> 5, lane = tid & 31;

    // stage 16 q-rows (512 octets, 2 per thread)
    for (int i = tid; i < 512; i += 256) {
        int r = i >> 5, g = i & 31;
        const float4* src =
            (const float4*)&q[((size_t)n * NQ + qbase + r) * NE + g * 8];
        qs[r][g] = pack8(src[0], src[1]);
    }
    if (tid < 32) {
        const float4* src = (const float4*)&wl[tid * 8];
        ws[tid] = pack8(src[0], src[1]);
    }
    // stage 32 v rows (1024 octets, 4 per thread)
    const int vbase = vb * 32;
    for (int i = tid; i < 1024; i += 256) {
        int v = i >> 5, g = i & 31;
        const float4* src =
            (const float4*)&c[((size_t)n * NV + vbase + v) * NE + g * 8];
        ct[g][v] = pack8(src[0], src[1]);
    }
    const float bl = __ldg(bl_p);
    const float invt = 1.0f / __ldg(temp_p);
    __syncthreads();

    const int r0 = w * 2, r1 = w * 2 + 1;
    float a0 = 0.f, a1 = 0.f;      // chain for q-row r0
    float b0 = 0.f, b1 = 0.f;      // chain for q-row r1
    #pragma unroll 4
    for (int g = 0; g < 32; ++g) {
        uint4 cb = ct[g][lane];
        uint4 qa = qs[r0][g];
        uint4 qb = qs[r1][g];
        uint4 wb = ws[g];

        __half2 pa0 = wtanh(cb.x, qa.x, wb.x);
        __half2 pb0 = wtanh(cb.x, qb.x, wb.x);
        __half2 pa1 = wtanh(cb.y, qa.y, wb.y);
        __half2 pb1 = wtanh(cb.y, qb.y, wb.y);
        __half2 pa2 = wtanh(cb.z, qa.z, wb.z);
        __half2 pb2 = wtanh(cb.z, qb.z, wb.z);
        __half2 pa3 = wtanh(cb.w, qa.w, wb.w);
        __half2 pb3 = wtanh(cb.w, qb.w, wb.w);

        __half2 psa = __hadd2(__hadd2(pa0, pa1), __hadd2(pa2, pa3));
        __half2 psb = __hadd2(__hadd2(pb0, pb1), __hadd2(pb2, pb3));
        float2 fa = __half22float2(psa);
        float2 fb = __half22float2(psb);
        a0 += fa.x; a1 += fa.y;
        b0 += fb.x; b1 += fb.y;
    }
    float e0 = __expf((a0 + a1 + bl) * invt);
    float e1 = __expf((b0 + b1 + bl) * invt);
    const size_t row0 = (size_t)n * NQ + qbase + r0;
    const size_t row1 = (size_t)n * NQ + qbase + r1;
    g_expl[row0 * NV + vbase + lane] = e0;
    g_expl[row1 * NV + vbase + lane] = e1;

    // per-row denominator partials (32 v each)
    float d0 = e0, d1 = e1;
    #pragma unroll
    for (int o = 16; o; o >>= 1) {
        d0 += __shfl_xor_sync(0xffffffffu, d0, o);
        d1 += __shfl_xor_sync(0xffffffffu, d1, o);
    }
    if (lane == 0) {
        g_denp[row0 * 16 + vb] = d0;
        g_denp[row1 * 16 + vb] = d1;
    }
}

// ---------------------------------------------------------------------------
// K2: split-4(K-slice 128) of e @ memory. r7 loop body (BK=16, 4x4 micro,
// plain fmaf); 256 blocks.
// ---------------------------------------------------------------------------
__global__ void __launch_bounds__(256) k_pv(const float* __restrict__ Mm)
{
    const int n = blockIdx.z >> 2, s = blockIdx.z & 3;
    const int m0 = blockIdx.y * 64, n0 = blockIdx.x * 64;
    const float* A = g_expl + (size_t)n * NQ * NV;
    const float* B = Mm + (size_t)n * NV * NE;

    __shared__ float As[16][68];
    __shared__ float Bs[16][68];

    const int tid = threadIdx.x;
    const int tx = tid & 15, ty = tid >> 4;
    const int ar = tid >> 2, ac = (tid & 3) * 4;
    const int br = tid >> 4, bc = (tid & 15) * 4;

    float acc[4][4] = {};

    for (int k0 = s * 128; k0 < s * 128 + 128; k0 += 16) {
        float4 av = *(const float4*)&A[(size_t)(m0 + ar) * NV + k0 + ac];
        As[ac][ar]     = av.x; As[ac + 1][ar] = av.y;
        As[ac + 2][ar] = av.z; As[ac + 3][ar] = av.w;
        *(float4*)&Bs[br][bc] =
            *(const float4*)&B[(size_t)(k0 + br) * NE + n0 + bc];
        __syncthreads();
        #pragma unroll
        for (int k = 0; k < 16; ++k) {
            float a[4], b[4];
            *(float4*)a = *(const float4*)&As[k][ty * 4];
            *(float4*)b = *(const float4*)&Bs[k][tx * 4];
            #pragma unroll
            for (int i = 0; i < 4; ++i)
                #pragma unroll
                for (int j = 0; j < 4; ++j)
                    acc[i][j] += a[i] * b[j];
        }
        __syncthreads();
    }

    float* P = g_pvp[s] + (size_t)n * NQ * NE;
    #pragma unroll
    for (int i = 0; i < 4; ++i)
        *(float4*)&P[(size_t)(m0 + ty * 4 + i) * NE + n0 + tx * 4] =
            make_float4(acc[i][0], acc[i][1], acc[i][2], acc[i][3]);
}

// ---------------------------------------------------------------------------
// K3: heads = leaky( (sum_s pvp) / (sum_vb denp) )
// ---------------------------------------------------------------------------
__global__ void __launch_bounds__(256) k_merge()
{
    const int i = blockIdx.x * 256 + threadIdx.x;   // float4 idx, 65536 total
    const int row = i >> 6;

    float dt = 0.f;
    #pragma unroll
    for (int vb = 0; vb < 16; ++vb) dt += g_denp[(size_t)row * 16 + vb];
    const float inv = 1.0f / dt;

    float4 sv = make_float4(0.f, 0.f, 0.f, 0.f);
    #pragma unroll
    for (int sp = 0; sp < 4; ++sp) {
        float4 p = *(const float4*)&g_pvp[sp][(size_t)i * 4];
        sv.x += p.x; sv.y += p.y; sv.z += p.z; sv.w += p.w;
    }
    float h0 = sv.x * inv, h1 = sv.y * inv, h2 = sv.z * inv, h3 = sv.w * inv;
    float4 r;
    r.x = (h0 > 0.f) ? h0 : 0.01f * h0;
    r.y = (h1 > 0.f) ? h1 : 0.01f * h1;
    r.z = (h2 > 0.f) ? h2 : 0.01f * h2;
    r.w = (h3 > 0.f) ? h3 : 0.01f * h3;
    *(float4*)&g_heads[(size_t)i * 4] = r;
}

// ---------------------------------------------------------------------------
// K4: split-4(K-slice 64) of heads @ Wr^T. EXACT r7 body.
// ---------------------------------------------------------------------------
__global__ void __launch_bounds__(256) k_out(const float* __restrict__ Wr)
{
    const int n = blockIdx.z >> 2, s = blockIdx.z & 3;
    const int m0 = blockIdx.y * 64, n0 = blockIdx.x * 64;
    const float* A = g_heads + (size_t)n * NQ * NE;

    __shared__ float As[16][68];
    __shared__ float Bs[16][68];

    const int tid = threadIdx.x;
    const int tx = tid & 15, ty = tid >> 4;
    const int ar = tid >> 2, ac = (tid & 3) * 4;

    float acc[4][4] = {};

    for (int k0 = s * 64; k0 < s * 64 + 64; k0 += 16) {
        float4 av = *(const float4*)&A[(size_t)(m0 + ar) * NE + k0 + ac];
        As[ac][ar]     = av.x; As[ac + 1][ar] = av.y;
        As[ac + 2][ar] = av.z; As[ac + 3][ar] = av.w;
        float4 bv = *(const float4*)&Wr[(size_t)(n0 + ar) * NE + k0 + ac];
        Bs[ac][ar]     = bv.x; Bs[ac + 1][ar] = bv.y;
        Bs[ac + 2][ar] = bv.z; Bs[ac + 3][ar] = bv.w;
        __syncthreads();
        #pragma unroll
        for (int k = 0; k < 16; ++k) {
            float a[4], b[4];
            *(float4*)a = *(const float4*)&As[k][ty * 4];
            *(float4*)b = *(const float4*)&Bs[k][tx * 4];
            #pragma unroll
            for (int i = 0; i < 4; ++i)
                #pragma unroll
                for (int j = 0; j < 4; ++j)
                    acc[i][j] += a[i] * b[j];
        }
        __syncthreads();
    }

    float* R = g_rdp[s] + (size_t)n * NQ * NE;
    #pragma unroll
    for (int i = 0; i < 4; ++i)
        *(float4*)&R[(size_t)(m0 + ty * 4 + i) * NE + n0 + tx * 4] =
            make_float4(acc[i][0], acc[i][1], acc[i][2], acc[i][3]);
}

// ---------------------------------------------------------------------------
// K5: out = sum of 4 reduce-partials + bias. EXACT r7 body.
// ---------------------------------------------------------------------------
__global__ void __launch_bounds__(256) k_final(
    const float* __restrict__ br_p, float* __restrict__ out)
{
    const int i = blockIdx.x * 256 + threadIdx.x;   // float4 idx, 65536 total
    const int col4 = i & 63;
    float4 r = *(const float4*)&br_p[col4 * 4];
    #pragma unroll
    for (int sp = 0; sp < 4; ++sp) {
        float4 p = *(const float4*)&g_rdp[sp][(size_t)i * 4];
        r.x += p.x; r.y += p.y; r.z += p.z; r.w += p.w;
    }
    *(float4*)&out[(size_t)i * 4] = r;
}

// ---------------------------------------------------------------------------
extern "C" void kernel_launch(void* const* d_in, const int* in_sizes, int n_in,
                              void* d_out, int out_size)
{
    const float* query   = (const float*)d_in[0];
    const float* context = (const float*)d_in[1];
    const float* memory  = (const float*)d_in[2];
    const float* w_logit = (const float*)d_in[3];
    const float* b_logit = (const float*)d_in[4];
    const float* temp    = (const float*)d_in[5];
    const float* w_red   = (const float*)d_in[6];
    const float* b_red   = (const float*)d_in[7];
    float* out = (float*)d_out;

    dim3 g1(NQ / 16, NV / 32, NN);       // 16 x 16 x 4 = 1024 blocks
    k_logits<<<g1, 256>>>(query, context, w_logit, b_logit, temp);

    dim3 g2(NE / 64, NQ / 64, NN * 4);   // 4 x 4 x 16 = 256 blocks
    k_pv<<<g2, 256>>>(memory);

    k_merge<<<256, 256>>>();             // 65536 float4

    dim3 g4(NE / 64, NQ / 64, NN * 4);   // 256 blocks
    k_out<<<g4, 256>>>(w_red);

    k_final<<<256, 256>>>(b_red, out);
}

// round 16
// speedup vs baseline: 1.5667x; 1.5667x over previous
#include <cuda_runtime.h>
#include <cuda_fp16.h>
#include <cuda_bf16.h>

#define NN 4
#define NQ 256
#define NV 512
#define NE 256

// Scratch (allocation-free requirement)
__device__ float g_expl[NN * NQ * NV];       // exp(logit/t)  (2 MB)
__device__ float g_denp[NN * NQ * 8];        // per-64v denominator partials
__device__ float g_pvp[8][NN * NQ * NE];     // split-8 partials of exp@memory (8 MB)
__device__ float g_heads[NN * NQ * NE];      // normalized, leaky heads (1 MB)
__device__ float g_rdp[4][NN * NQ * NE];     // split-4 partials of heads@Wr^T (4 MB)

// ---------------------------------------------------------------------------
// helpers
// ---------------------------------------------------------------------------
__device__ __forceinline__ uint4 pack8(const float4 a, const float4 b) {
    __half2 h0 = __floats2half2_rn(a.x, a.y);
    __half2 h1 = __floats2half2_rn(a.z, a.w);
    __half2 h2 = __floats2half2_rn(b.x, b.y);
    __half2 h3 = __floats2half2_rn(b.z, b.w);
    uint4 r;
    r.x = *reinterpret_cast<unsigned*>(&h0);
    r.y = *reinterpret_cast<unsigned*>(&h1);
    r.z = *reinterpret_cast<unsigned*>(&h2);
    r.w = *reinterpret_cast<unsigned*>(&h3);
    return r;
}

__device__ __forceinline__ __half2 u2h(unsigned u) {
    return *reinterpret_cast<__half2*>(&u);
}

// tanh of (q+c) in f16x2, times w (f16x2)
__device__ __forceinline__ __half2 wtanh(unsigned cv, unsigned qv, unsigned wv) {
    __half2 s = __hadd2(u2h(qv), u2h(cv));
    unsigned su = *reinterpret_cast<unsigned*>(&s);
    unsigned tu;
    asm("tanh.approx.f16x2 %0, %1;" : "=r"(tu) : "r"(su));
    return __hmul2(u2h(tu), u2h(wv));
}

// ---------------------------------------------------------------------------
// K1: e[n,q,v] = exp( (sum_e w*tanh(q+c) + b) / t ), plus per-64v denom
// partials. Warp = q-row, lane = v. f16x2 tanh octet pipeline.
// ct row stride 33 uint4 (== 4 mod 32 words): conflict-free LDS.128 & STS.128.
// ---------------------------------------------------------------------------
__global__ void __launch_bounds__(256) k_logits(
    const float* __restrict__ q, const float* __restrict__ c,
    const float* __restrict__ wl, const float* __restrict__ bl_p,
    const float* __restrict__ temp_p)
{
    __shared__ uint4 ct[32][33];    // 16.9 KB, [e-octet][v]
    __shared__ uint4 qs[8][32];     // 4 KB
    __shared__ uint4 ws[32];        // 512 B

    const int n = blockIdx.z;
    const int qbase = blockIdx.x * 8;
    const int tid = threadIdx.x;
    const int wq = tid >> 5, lane = tid & 31;

    {   // one q-octet per thread
        int r = tid >> 5, g = tid & 31;
        const float4* src =
            (const float4*)&q[((size_t)n * NQ + qbase + r) * NE + g * 8];
        qs[r][g] = pack8(src[0], src[1]);
    }
    if (tid < 32) {
        const float4* src = (const float4*)&wl[tid * 8];
        ws[tid] = pack8(src[0], src[1]);
    }
    const float bl = __ldg(bl_p);
    const float invt = 1.0f / __ldg(temp_p);

    float dsum = 0.f;
    #pragma unroll
    for (int t = 0; t < 2; ++t) {
        __syncthreads();
        const int vbase = blockIdx.y * 64 + t * 32;
        for (int i = tid; i < 1024; i += 256) {   // 32 v x 32 octets
            int v = i >> 5, g = i & 31;
            const float4* src =
                (const float4*)&c[((size_t)n * NV + vbase + v) * NE + g * 8];
            ct[g][v] = pack8(src[0], src[1]);
        }
        __syncthreads();

        float a0 = 0.f, a1 = 0.f;
        #pragma unroll 8
        for (int g = 0; g < 32; ++g) {
            uint4 cb = ct[g][lane];
            uint4 qb = qs[wq][g];
            uint4 wb = ws[g];
            __half2 p0 = wtanh(cb.x, qb.x, wb.x);
            __half2 p1 = wtanh(cb.y, qb.y, wb.y);
            __half2 p2 = wtanh(cb.z, qb.z, wb.z);
            __half2 p3 = wtanh(cb.w, qb.w, wb.w);
            __half2 ps = __hadd2(__hadd2(p0, p1), __hadd2(p2, p3));
            float2 f = __half22float2(ps);
            a0 += f.x;
            a1 += f.y;
        }
        float e = __expf((a0 + a1 + bl) * invt);
        dsum += e;
        g_expl[((size_t)n * NQ + qbase + wq) * NV + vbase + lane] = e;
    }

    // warp-reduce dsum over 32 lanes (this block's 64 v's for row wq)
    #pragma unroll
    for (int o = 16; o; o >>= 1) dsum += __shfl_xor_sync(0xffffffffu, dsum, o);
    if (lane == 0)
        g_denp[((size_t)n * NQ + qbase + wq) * 8 + blockIdx.y] = dsum;
}

// ---------------------------------------------------------------------------
// K2: split-8(K-slice 64) of e @ memory. Plain copy A-staging, BK=16,
// 4x4 micro-tile, plain fmaf (r2-proven loop shape).
// ---------------------------------------------------------------------------
__global__ void __launch_bounds__(256) k_pv(const float* __restrict__ Mm)
{
    const int n = blockIdx.z >> 3, s = blockIdx.z & 7;
    const int m0 = blockIdx.y * 64, n0 = blockIdx.x * 64;
    const float* A = g_expl + (size_t)n * NQ * NV;
    const float* B = Mm + (size_t)n * NV * NE;

    __shared__ float As[16][68];
    __shared__ float Bs[16][68];

    const int tid = threadIdx.x;
    const int tx = tid & 15, ty = tid >> 4;
    const int ar = tid >> 2, ac = (tid & 3) * 4;  // A: 64 rows x 16 k
    const int br = tid >> 4, bc = (tid & 15) * 4; // B: 16 rows x 64 n

    float acc[4][4] = {};

    for (int k0 = s * 64; k0 < s * 64 + 64; k0 += 16) {
        float4 av = *(const float4*)&A[(size_t)(m0 + ar) * NV + k0 + ac];
        As[ac][ar]     = av.x; As[ac + 1][ar] = av.y;
        As[ac + 2][ar] = av.z; As[ac + 3][ar] = av.w;
        *(float4*)&Bs[br][bc] =
            *(const float4*)&B[(size_t)(k0 + br) * NE + n0 + bc];
        __syncthreads();
        #pragma unroll
        for (int k = 0; k < 16; ++k) {
            float a[4], b[4];
            *(float4*)a = *(const float4*)&As[k][ty * 4];
            *(float4*)b = *(const float4*)&Bs[k][tx * 4];
            #pragma unroll
            for (int i = 0; i < 4; ++i)
                #pragma unroll
                for (int j = 0; j < 4; ++j)
                    acc[i][j] += a[i] * b[j];
        }
        __syncthreads();
    }

    float* P = g_pvp[s] + (size_t)n * NQ * NE;
    #pragma unroll
    for (int i = 0; i < 4; ++i)
        *(float4*)&P[(size_t)(m0 + ty * 4 + i) * NE + n0 + tx * 4] =
            make_float4(acc[i][0], acc[i][1], acc[i][2], acc[i][3]);
}

// ---------------------------------------------------------------------------
// K3: heads = leaky( (sum_s pvp) / (sum_vb denp) )
// ---------------------------------------------------------------------------
__global__ void __launch_bounds__(256) k_merge()
{
    const int i = blockIdx.x * 256 + threadIdx.x;   // float4 idx, 65536 total
    const int row = i >> 6;

    float dt = 0.f;
    #pragma unroll
    for (int vb = 0; vb < 8; ++vb) dt += g_denp[(size_t)row * 8 + vb];
    const float inv = 1.0f / dt;

    float4 sv = make_float4(0.f, 0.f, 0.f, 0.f);
    #pragma unroll
    for (int sp = 0; sp < 8; ++sp) {
        float4 p = *(const float4*)&g_pvp[sp][(size_t)i * 4];
        sv.x += p.x; sv.y += p.y; sv.z += p.z; sv.w += p.w;
    }
    float h0 = sv.x * inv, h1 = sv.y * inv, h2 = sv.z * inv, h3 = sv.w * inv;
    float4 r;
    r.x = (h0 > 0.f) ? h0 : 0.01f * h0;
    r.y = (h1 > 0.f) ? h1 : 0.01f * h1;
    r.z = (h2 > 0.f) ? h2 : 0.01f * h2;
    r.w = (h3 > 0.f) ? h3 : 0.01f * h3;
    *(float4*)&g_heads[(size_t)i * 4] = r;
}

// ---------------------------------------------------------------------------
// K4: split-4(K-slice 64) of heads @ Wr^T. 64x64 tiles, BK=16, 4x4 micro,
// plain fmaf, B transposed during staging. Writes partials.
// ---------------------------------------------------------------------------
__global__ void __launch_bounds__(256) k_out(const float* __restrict__ Wr)
{
    const int n = blockIdx.z >> 2, s = blockIdx.z & 3;
    const int m0 = blockIdx.y * 64, n0 = blockIdx.x * 64;
    const float* A = g_heads + (size_t)n * NQ * NE;

    __shared__ float As[16][68];
    __shared__ float Bs[16][68];

    const int tid = threadIdx.x;
    const int tx = tid & 15, ty = tid >> 4;
    const int ar = tid >> 2, ac = (tid & 3) * 4;

    float acc[4][4] = {};

    for (int k0 = s * 64; k0 < s * 64 + 64; k0 += 16) {
        float4 av = *(const float4*)&A[(size_t)(m0 + ar) * NE + k0 + ac];
        As[ac][ar]     = av.x; As[ac + 1][ar] = av.y;
        As[ac + 2][ar] = av.z; As[ac + 3][ar] = av.w;
        // Bs[k][j] = Wr[(n0+j)*NE + k0+k]  (transpose during staging)
        float4 bv = *(const float4*)&Wr[(size_t)(n0 + ar) * NE + k0 + ac];
        Bs[ac][ar]     = bv.x; Bs[ac + 1][ar] = bv.y;
        Bs[ac + 2][ar] = bv.z; Bs[ac + 3][ar] = bv.w;
        __syncthreads();
        #pragma unroll
        for (int k = 0; k < 16; ++k) {
            float a[4], b[4];
            *(float4*)a = *(const float4*)&As[k][ty * 4];
            *(float4*)b = *(const float4*)&Bs[k][tx * 4];
            #pragma unroll
            for (int i = 0; i < 4; ++i)
                #pragma unroll
                for (int j = 0; j < 4; ++j)
                    acc[i][j] += a[i] * b[j];
        }
        __syncthreads();
    }

    float* R = g_rdp[s] + (size_t)n * NQ * NE;
    #pragma unroll
    for (int i = 0; i < 4; ++i)
        *(float4*)&R[(size_t)(m0 + ty * 4 + i) * NE + n0 + tx * 4] =
            make_float4(acc[i][0], acc[i][1], acc[i][2], acc[i][3]);
}

// ---------------------------------------------------------------------------
// K5: out = sum of 4 reduce-partials + bias
// ---------------------------------------------------------------------------
__global__ void __launch_bounds__(256) k_final(
    const float* __restrict__ br_p, float* __restrict__ out)
{
    const int i = blockIdx.x * 256 + threadIdx.x;   // float4 idx, 65536 total
    const int col4 = i & 63;
    float4 r = *(const float4*)&br_p[col4 * 4];
    #pragma unroll
    for (int sp = 0; sp < 4; ++sp) {
        float4 p = *(const float4*)&g_rdp[sp][(size_t)i * 4];
        r.x += p.x; r.y += p.y; r.z += p.z; r.w += p.w;
    }
    *(float4*)&out[(size_t)i * 4] = r;
}

// ---------------------------------------------------------------------------
extern "C" void kernel_launch(void* const* d_in, const int* in_sizes, int n_in,
                              void* d_out, int out_size)
{
    const float* query   = (const float*)d_in[0];
    const float* context = (const float*)d_in[1];
    const float* memory  = (const float*)d_in[2];
    const float* w_logit = (const float*)d_in[3];
    const float* b_logit = (const float*)d_in[4];
    const float* temp    = (const float*)d_in[5];
    const float* w_red   = (const float*)d_in[6];
    const float* b_red   = (const float*)d_in[7];
    float* out = (float*)d_out;

    dim3 g1(NQ / 8, NV / 64, NN);        // 32 x 8 x 4 = 1024 blocks
    k_logits<<<g1, 256>>>(query, context, w_logit, b_logit, temp);

    dim3 g2(NE / 64, NQ / 64, NN * 8);   // 4 x 4 x 32 = 512 blocks
    k_pv<<<g2, 256>>>(memory);

    k_merge<<<256, 256>>>();             // 65536 float4

    dim3 g4(NE / 64, NQ / 64, NN * 4);   // 4 x 4 x 16 = 256 blocks
    k_out<<<g4, 256>>>(w_red);

    k_final<<<256, 256>>>(b_red, out);
}